// round 1
// baseline (speedup 1.0000x reference)
#include <cuda_runtime.h>

#define B_  65536
#define T_  28
#define IN_ 28
#define HE_ 4
#define HD_ 28
#define NC_ 10

// shared-memory weight layout (float offsets; every section float4-aligned)
#define O_EWIH 0      // enc_Wih [16,28]  = 448
#define O_EWHH 448    // enc_Whh [16,4]   = 64
#define O_EB   512    // enc_b   [16]
#define O_DWIH 528    // dec_Wih [112,4]  = 448
#define O_DWHH 976    // dec_Whh [112,28] = 3136
#define O_DB   4112   // dec_b   [112]
#define O_UW   4224   // U_W     [10,28]  = 280
#define O_UB   4504   // U_b     [10]
#define W_TOT  4516

__device__ __forceinline__ float sigm(float v) {
    return __fdividef(1.0f, 1.0f + __expf(-v));
}
__device__ __forceinline__ float tanh_f(float v) {
    // 1 - 2/(e^{2v}+1): no inf/inf, mild cancellation only near 0 (abs err ~1e-7)
    float e = __expf(2.0f * v);
    return 1.0f - __fdividef(2.0f, e + 1.0f);
}

__global__ void __launch_bounds__(128, 4)
ae_lstm_kernel(const float* __restrict__ x,
               const float* __restrict__ eWih, const float* __restrict__ eWhh,
               const float* __restrict__ eb,
               const float* __restrict__ dWih, const float* __restrict__ dWhh,
               const float* __restrict__ db,
               const float* __restrict__ uW,  const float* __restrict__ ubv,
               float* __restrict__ out, float* __restrict__ pred)
{
    __shared__ __align__(16) float w[W_TOT];
    for (int i = threadIdx.x; i < 448;  i += blockDim.x) w[O_EWIH + i] = eWih[i];
    for (int i = threadIdx.x; i < 64;   i += blockDim.x) w[O_EWHH + i] = eWhh[i];
    for (int i = threadIdx.x; i < 16;   i += blockDim.x) w[O_EB   + i] = eb[i];
    for (int i = threadIdx.x; i < 448;  i += blockDim.x) w[O_DWIH + i] = dWih[i];
    for (int i = threadIdx.x; i < 3136; i += blockDim.x) w[O_DWHH + i] = dWhh[i];
    for (int i = threadIdx.x; i < 112;  i += blockDim.x) w[O_DB   + i] = db[i];
    for (int i = threadIdx.x; i < 280;  i += blockDim.x) w[O_UW   + i] = uW[i];
    for (int i = threadIdx.x; i < 10;   i += blockDim.x) w[O_UB   + i] = ubv[i];
    __syncthreads();

    int b = blockIdx.x * blockDim.x + threadIdx.x;
    if (b >= B_) return;

    float he[HE_] = {0.f,0.f,0.f,0.f};
    float ce[HE_] = {0.f,0.f,0.f,0.f};
    float hd[HD_], cd[HD_];
#pragma unroll
    for (int j = 0; j < HD_; ++j) { hd[j] = 0.f; cd[j] = 0.f; }

    const float4* xb = (const float4*)(x   + (size_t)b * T_ * IN_);
    float4*       ob = (float4*)      (out + (size_t)b * T_ * HD_);

    const float4* ewih4 = (const float4*)(w + O_EWIH); // 16 rows x 7 float4
    const float4* ewhh4 = (const float4*)(w + O_EWHH); // 16 rows x 1 float4
    const float4* dwih4 = (const float4*)(w + O_DWIH); // 112 rows x 1 float4
    const float4* dwhh4 = (const float4*)(w + O_DWHH); // 112 rows x 7 float4

#pragma unroll 1
    for (int t = 0; t < T_; ++t) {
        // ---- load x row (28 consecutive floats, 7x LDG.128) ----
        float xr[IN_];
#pragma unroll
        for (int q = 0; q < 7; ++q) {
            float4 v = xb[t * 7 + q];
            xr[4*q+0] = v.x; xr[4*q+1] = v.y; xr[4*q+2] = v.z; xr[4*q+3] = v.w;
        }

        // ---- encoder LSTM step (H=4) ----
        float hen[HE_];
#pragma unroll
        for (int j = 0; j < HE_; ++j) {
            float gi = w[O_EB + j];
            float gf = w[O_EB + 4  + j];
            float gg = w[O_EB + 8  + j];
            float go = w[O_EB + 12 + j];
#pragma unroll
            for (int q = 0; q < 7; ++q) {
                float4 ai = ewih4[(j     ) * 7 + q];
                float4 af = ewih4[(4  + j) * 7 + q];
                float4 ag = ewih4[(8  + j) * 7 + q];
                float4 ao = ewih4[(12 + j) * 7 + q];
                float x0 = xr[4*q+0], x1 = xr[4*q+1], x2 = xr[4*q+2], x3 = xr[4*q+3];
                gi += ai.x*x0 + ai.y*x1 + ai.z*x2 + ai.w*x3;
                gf += af.x*x0 + af.y*x1 + af.z*x2 + af.w*x3;
                gg += ag.x*x0 + ag.y*x1 + ag.z*x2 + ag.w*x3;
                go += ao.x*x0 + ao.y*x1 + ao.z*x2 + ao.w*x3;
            }
            {
                float4 hi = ewhh4[j], hf = ewhh4[4 + j], hg = ewhh4[8 + j], ho = ewhh4[12 + j];
                gi += hi.x*he[0] + hi.y*he[1] + hi.z*he[2] + hi.w*he[3];
                gf += hf.x*he[0] + hf.y*he[1] + hf.z*he[2] + hf.w*he[3];
                gg += hg.x*he[0] + hg.y*he[1] + hg.z*he[2] + hg.w*he[3];
                go += ho.x*he[0] + ho.y*he[1] + ho.z*he[2] + ho.w*he[3];
            }
            float c = sigm(gf) * ce[j] + sigm(gi) * tanh_f(gg);
            ce[j]  = c;
            hen[j] = sigm(go) * tanh_f(c);
        }
#pragma unroll
        for (int j = 0; j < HE_; ++j) he[j] = hen[j];

        // ---- decoder LSTM step (H=28), input = he ----
        float hdn[HD_];
#pragma unroll
        for (int j = 0; j < HD_; ++j) {
            float gi = w[O_DB + j];
            float gf = w[O_DB + 28 + j];
            float gg = w[O_DB + 56 + j];
            float go = w[O_DB + 84 + j];
            {
                float4 ii = dwih4[j], jf = dwih4[28 + j], jg = dwih4[56 + j], jo = dwih4[84 + j];
                gi += ii.x*he[0] + ii.y*he[1] + ii.z*he[2] + ii.w*he[3];
                gf += jf.x*he[0] + jf.y*he[1] + jf.z*he[2] + jf.w*he[3];
                gg += jg.x*he[0] + jg.y*he[1] + jg.z*he[2] + jg.w*he[3];
                go += jo.x*he[0] + jo.y*he[1] + jo.z*he[2] + jo.w*he[3];
            }
#pragma unroll
            for (int q = 0; q < 7; ++q) {
                float4 ai = dwhh4[(j     ) * 7 + q];
                float4 af = dwhh4[(28 + j) * 7 + q];
                float4 ag = dwhh4[(56 + j) * 7 + q];
                float4 ao = dwhh4[(84 + j) * 7 + q];
                float h0 = hd[4*q+0], h1 = hd[4*q+1], h2 = hd[4*q+2], h3 = hd[4*q+3];
                gi += ai.x*h0 + ai.y*h1 + ai.z*h2 + ai.w*h3;
                gf += af.x*h0 + af.y*h1 + af.z*h2 + af.w*h3;
                gg += ag.x*h0 + ag.y*h1 + ag.z*h2 + ag.w*h3;
                go += ao.x*h0 + ao.y*h1 + ao.z*h2 + ao.w*h3;
            }
            float c = sigm(gf) * cd[j] + sigm(gi) * tanh_f(gg);
            cd[j]  = c;
            hdn[j] = sigm(go) * tanh_f(c);
        }
#pragma unroll
        for (int j = 0; j < HD_; ++j) hd[j] = hdn[j];

        // ---- write decoder output row (7x STG.128) ----
#pragma unroll
        for (int q = 0; q < 7; ++q) {
            float4 v;
            v.x = hd[4*q+0]; v.y = hd[4*q+1]; v.z = hd[4*q+2]; v.w = hd[4*q+3];
            ob[t * 7 + q] = v;
        }
    }

    // ---- classifier head on final decoder h: logits + softmax ----
    const float4* uw4 = (const float4*)(w + O_UW);
    float lg[NC_];
    float m = -3.4e38f;
#pragma unroll
    for (int k = 0; k < NC_; ++k) {
        float a = w[O_UB + k];
#pragma unroll
        for (int q = 0; q < 7; ++q) {
            float4 u = uw4[k * 7 + q];
            a += u.x*hd[4*q+0] + u.y*hd[4*q+1] + u.z*hd[4*q+2] + u.w*hd[4*q+3];
        }
        lg[k] = a;
        m = fmaxf(m, a);
    }
    float s = 0.f;
#pragma unroll
    for (int k = 0; k < NC_; ++k) { float e = __expf(lg[k] - m); lg[k] = e; s += e; }
    float inv = __fdividef(1.0f, s);
#pragma unroll
    for (int k = 0; k < NC_; ++k) pred[(size_t)b * NC_ + k] = lg[k] * inv;
}

extern "C" void kernel_launch(void* const* d_in, const int* in_sizes, int n_in,
                              void* d_out, int out_size)
{
    const float* x    = (const float*)d_in[0];
    const float* eWih = (const float*)d_in[1];
    const float* eWhh = (const float*)d_in[2];
    const float* eb   = (const float*)d_in[3];
    const float* dWih = (const float*)d_in[4];
    const float* dWhh = (const float*)d_in[5];
    const float* db   = (const float*)d_in[6];
    const float* uW   = (const float*)d_in[7];
    const float* ub   = (const float*)d_in[8];

    float* out  = (float*)d_out;                          // [B, T, 28]
    float* pred = out + (size_t)B_ * T_ * HD_;            // [1, B, 10]

    dim3 grid(B_ / 128), block(128);
    ae_lstm_kernel<<<grid, block>>>(x, eWih, eWhh, eb, dWih, dWhh, db, uW, ub,
                                    out, pred);
}

// round 2
// speedup vs baseline: 1.0815x; 1.0815x over previous
#include <cuda_runtime.h>

#define B_  65536
#define T_  28
#define IN_ 28
#define HE_ 4
#define HD_ 28
#define NC_ 10

// shared-memory weight layout (float offsets; every section & row 16B-aligned)
#define O_EWIH 0      // enc_Wih [16,28]  = 448
#define O_EWHH 448    // enc_Whh [16,4]   = 64
#define O_EB   512    // enc_b   [16]
#define O_DWIH 528    // dec_Wih [112,4]  = 448
#define O_DWHH 976    // dec_Whh [112,28] = 3136
#define O_DB   4112   // dec_b   [112]
#define O_UW   4224   // U_W     [10,28]  = 280
#define O_UB   4504   // U_b     [10]
#define W_TOT  4516

// ulonglong2 (16B) indices into the same smem array
#define U_EWIH 0            // row r: idx r*7  (+q)
#define U_EWHH 112          // row r: idx 112 + r
#define U_DWIH 132          // row r: idx 132 + r
#define U_DWHH 244          // row r: idx 244 + r*7 (+q)
#define U_UW   1056         // row k: idx 1056 + k*7 (+q)

typedef unsigned long long ull;

__device__ __forceinline__ void fma2(ull& acc, ull a, ull b) {
    asm("fma.rn.f32x2 %0, %1, %2, %0;" : "+l"(acc) : "l"(a), "l"(b));
}
__device__ __forceinline__ ull pack2(float lo, float hi) {
    ull r; asm("mov.b64 %0, {%1, %2};" : "=l"(r) : "f"(lo), "f"(hi)); return r;
}
__device__ __forceinline__ float hadd2(ull v) {
    float lo, hi; asm("mov.b64 {%0, %1}, %2;" : "=f"(lo), "=f"(hi) : "l"(v));
    return lo + hi;
}
__device__ __forceinline__ float sigm(float v) {
    return __fdividef(1.0f, 1.0f + __expf(-v));
}
__device__ __forceinline__ float tanh_f(float v) {
    float e = __expf(2.0f * v);
    return 1.0f - __fdividef(2.0f, e + 1.0f);
}

__global__ void __launch_bounds__(128, 6)
ae_lstm_kernel(const float* __restrict__ x,
               const float* __restrict__ eWih, const float* __restrict__ eWhh,
               const float* __restrict__ eb,
               const float* __restrict__ dWih, const float* __restrict__ dWhh,
               const float* __restrict__ db,
               const float* __restrict__ uW,  const float* __restrict__ ubv,
               float* __restrict__ out, float* __restrict__ pred)
{
    __shared__ __align__(16) float w[W_TOT];
    for (int i = threadIdx.x; i < 448;  i += blockDim.x) w[O_EWIH + i] = eWih[i];
    for (int i = threadIdx.x; i < 64;   i += blockDim.x) w[O_EWHH + i] = eWhh[i];
    for (int i = threadIdx.x; i < 16;   i += blockDim.x) w[O_EB   + i] = eb[i];
    for (int i = threadIdx.x; i < 448;  i += blockDim.x) w[O_DWIH + i] = dWih[i];
    for (int i = threadIdx.x; i < 3136; i += blockDim.x) w[O_DWHH + i] = dWhh[i];
    for (int i = threadIdx.x; i < 112;  i += blockDim.x) w[O_DB   + i] = db[i];
    for (int i = threadIdx.x; i < 280;  i += blockDim.x) w[O_UW   + i] = uW[i];
    for (int i = threadIdx.x; i < 10;   i += blockDim.x) w[O_UB   + i] = ubv[i];
    __syncthreads();

    const ulonglong2* W2 = (const ulonglong2*)w;

    const int p = threadIdx.x & 3;                      // part id within sample
    const int b = blockIdx.x * 32 + (threadIdx.x >> 2); // sample id

    const ulonglong2* xb = (const ulonglong2*)(x + (size_t)b * T_ * IN_); // 7 u2/row
    float* ob = out + (size_t)b * T_ * HD_ + p * 7;     // this thread's 7 outputs/row

    // persistent state
    ull   hd64[14];                  // full decoder h, packed (h_{2m}, h_{2m+1})
    float cd[7];                     // cell state of own 7 decoder units
    ull   hep[2];                    // full encoder h packed
    float ce = 0.f;                  // cell state of own encoder unit
#pragma unroll
    for (int m = 0; m < 14; ++m) hd64[m] = 0ull;
#pragma unroll
    for (int u = 0; u < 7; ++u) cd[u] = 0.f;
    hep[0] = 0ull; hep[1] = 0ull;

#pragma unroll 1
    for (int t = 0; t < T_; ++t) {
        // ================= encoder: this thread computes unit p =================
        ull ea0 = pack2(w[O_EB + 0  + p], 0.f);
        ull ea1 = pack2(w[O_EB + 4  + p], 0.f);
        ull ea2 = pack2(w[O_EB + 8  + p], 0.f);
        ull ea3 = pack2(w[O_EB + 12 + p], 0.f);
#pragma unroll
        for (int q = 0; q < 7; ++q) {
            ulonglong2 xv = xb[t * 7 + q];
            ulonglong2 w0 = W2[U_EWIH + (0  + p) * 7 + q];
            ulonglong2 w1 = W2[U_EWIH + (4  + p) * 7 + q];
            ulonglong2 w2 = W2[U_EWIH + (8  + p) * 7 + q];
            ulonglong2 w3 = W2[U_EWIH + (12 + p) * 7 + q];
            fma2(ea0, w0.x, xv.x); fma2(ea0, w0.y, xv.y);
            fma2(ea1, w1.x, xv.x); fma2(ea1, w1.y, xv.y);
            fma2(ea2, w2.x, xv.x); fma2(ea2, w2.y, xv.y);
            fma2(ea3, w3.x, xv.x); fma2(ea3, w3.y, xv.y);
        }
        {
            ulonglong2 w0 = W2[U_EWHH + 0  + p];
            ulonglong2 w1 = W2[U_EWHH + 4  + p];
            ulonglong2 w2 = W2[U_EWHH + 8  + p];
            ulonglong2 w3 = W2[U_EWHH + 12 + p];
            fma2(ea0, w0.x, hep[0]); fma2(ea0, w0.y, hep[1]);
            fma2(ea1, w1.x, hep[0]); fma2(ea1, w1.y, hep[1]);
            fma2(ea2, w2.x, hep[0]); fma2(ea2, w2.y, hep[1]);
            fma2(ea3, w3.x, hep[0]); fma2(ea3, w3.y, hep[1]);
        }
        {
            float gi = hadd2(ea0), gf = hadd2(ea1), gg = hadd2(ea2), go = hadd2(ea3);
            float c  = sigm(gf) * ce + sigm(gi) * tanh_f(gg);
            ce = c;
            float heo = sigm(go) * tanh_f(c);
            float h0 = __shfl_sync(0xffffffffu, heo, 0, 4);
            float h1 = __shfl_sync(0xffffffffu, heo, 1, 4);
            float h2 = __shfl_sync(0xffffffffu, heo, 2, 4);
            float h3 = __shfl_sync(0xffffffffu, heo, 3, 4);
            hep[0] = pack2(h0, h1);
            hep[1] = pack2(h2, h3);
        }

        // ================= decoder: this thread computes units 7p..7p+6 =================
        float hnew[7];
#pragma unroll
        for (int u = 0; u < 7; ++u) {
            const int j = p * 7 + u;
            ull a0 = pack2(w[O_DB + j],      0.f);
            ull a1 = pack2(w[O_DB + 28 + j], 0.f);
            ull a2 = pack2(w[O_DB + 56 + j], 0.f);
            ull a3 = pack2(w[O_DB + 84 + j], 0.f);
            {   // input projection (he, 4 wide)
                ulonglong2 w0 = W2[U_DWIH + j];
                ulonglong2 w1 = W2[U_DWIH + 28 + j];
                ulonglong2 w2 = W2[U_DWIH + 56 + j];
                ulonglong2 w3 = W2[U_DWIH + 84 + j];
                fma2(a0, w0.x, hep[0]); fma2(a0, w0.y, hep[1]);
                fma2(a1, w1.x, hep[0]); fma2(a1, w1.y, hep[1]);
                fma2(a2, w2.x, hep[0]); fma2(a2, w2.y, hep[1]);
                fma2(a3, w3.x, hep[0]); fma2(a3, w3.y, hep[1]);
            }
#pragma unroll
            for (int q = 0; q < 7; ++q) {
                ulonglong2 w0 = W2[U_DWHH + (j     ) * 7 + q];
                ulonglong2 w1 = W2[U_DWHH + (28 + j) * 7 + q];
                ulonglong2 w2 = W2[U_DWHH + (56 + j) * 7 + q];
                ulonglong2 w3 = W2[U_DWHH + (84 + j) * 7 + q];
                ull hlo = hd64[2 * q], hhi = hd64[2 * q + 1];
                fma2(a0, w0.x, hlo); fma2(a0, w0.y, hhi);
                fma2(a1, w1.x, hlo); fma2(a1, w1.y, hhi);
                fma2(a2, w2.x, hlo); fma2(a2, w2.y, hhi);
                fma2(a3, w3.x, hlo); fma2(a3, w3.y, hhi);
            }
            float gi = hadd2(a0), gf = hadd2(a1), gg = hadd2(a2), go = hadd2(a3);
            float c  = sigm(gf) * cd[u] + sigm(gi) * tanh_f(gg);
            cd[u]   = c;
            hnew[u] = sigm(go) * tanh_f(c);
        }

        // store own 7 outputs (scalar, constant indices)
#pragma unroll
        for (int u = 0; u < 7; ++u) ob[t * HD_ + u] = hnew[u];

        // exchange full decoder h, packing pairs directly
#pragma unroll
        for (int m = 0; m < 14; ++m) {
            float lo = __shfl_sync(0xffffffffu, hnew[(2 * m)     % 7], (2 * m)     / 7, 4);
            float hi = __shfl_sync(0xffffffffu, hnew[(2 * m + 1) % 7], (2 * m + 1) / 7, 4);
            hd64[m] = pack2(lo, hi);
        }
    }

    // ================= classifier head on final decoder h =================
    float lg[NC_];
    float mx = -3.4e38f;
#pragma unroll
    for (int k = 0; k < NC_; ++k) {
        ull a = pack2(w[O_UB + k], 0.f);
#pragma unroll
        for (int q = 0; q < 7; ++q) {
            ulonglong2 uv = W2[U_UW + k * 7 + q];
            fma2(a, uv.x, hd64[2 * q]);
            fma2(a, uv.y, hd64[2 * q + 1]);
        }
        lg[k] = hadd2(a);
        mx = fmaxf(mx, lg[k]);
    }
    float s = 0.f;
#pragma unroll
    for (int k = 0; k < NC_; ++k) { float e = __expf(lg[k] - mx); lg[k] = e; s += e; }
    float inv = __fdividef(1.0f, s);

    if (p == 0) {
        float2* pp = (float2*)(pred + (size_t)b * NC_);   // 8B-aligned (40*b bytes)
        pp[0] = make_float2(lg[0] * inv, lg[1] * inv);
        pp[1] = make_float2(lg[2] * inv, lg[3] * inv);
        pp[2] = make_float2(lg[4] * inv, lg[5] * inv);
        pp[3] = make_float2(lg[6] * inv, lg[7] * inv);
        pp[4] = make_float2(lg[8] * inv, lg[9] * inv);
    }
}

extern "C" void kernel_launch(void* const* d_in, const int* in_sizes, int n_in,
                              void* d_out, int out_size)
{
    const float* x    = (const float*)d_in[0];
    const float* eWih = (const float*)d_in[1];
    const float* eWhh = (const float*)d_in[2];
    const float* eb   = (const float*)d_in[3];
    const float* dWih = (const float*)d_in[4];
    const float* dWhh = (const float*)d_in[5];
    const float* db   = (const float*)d_in[6];
    const float* uW   = (const float*)d_in[7];
    const float* ub   = (const float*)d_in[8];

    float* out  = (float*)d_out;                 // [B, T, 28]
    float* pred = out + (size_t)B_ * T_ * HD_;   // [1, B, 10]

    dim3 grid(B_ / 32), block(128);              // 4 threads per sample
    ae_lstm_kernel<<<grid, block>>>(x, eWih, eWhh, eb, dWih, dWhh, db, uW, ub,
                                    out, pred);
}

// round 3
// speedup vs baseline: 1.2688x; 1.1732x over previous
#include <cuda_runtime.h>

#define B_  65536
#define T_  28
#define IN_ 28
#define HD_ 28
#define NC_ 10

typedef unsigned long long ull;

__device__ __forceinline__ ull pack2(float lo, float hi) {
    ull r; asm("mov.b64 %0, {%1, %2};" : "=l"(r) : "f"(lo), "f"(hi)); return r;
}
__device__ __forceinline__ void fma2(ull& acc, ull a, ull b) {
    asm("fma.rn.f32x2 %0, %1, %2, %0;" : "+l"(acc) : "l"(a), "l"(b));
}
__device__ __forceinline__ float hadd2(ull v) {
    float lo, hi; asm("mov.b64 {%0, %1}, %2;" : "=f"(lo), "=f"(hi) : "l"(v));
    return lo + hi;
}
__device__ __forceinline__ float sigm(float v) {
    return __fdividef(1.0f, 1.0f + __expf(-v));
}
__device__ __forceinline__ float tanh_f(float v) {
    float e = __expf(2.0f * v);
    return 1.0f - __fdividef(2.0f, e + 1.0f);
}

// block = 128 threads = 4 warps = 4 samples; weights register-stationary per lane.
__global__ void __launch_bounds__(128, 2)
ae_lstm_kernel(const float* __restrict__ x,
               const float* __restrict__ eWih, const float* __restrict__ eWhh,
               const float* __restrict__ eb,
               const float* __restrict__ dWih, const float* __restrict__ dWhh,
               const float* __restrict__ db,
               const float* __restrict__ uW,  const float* __restrict__ ubv,
               float* __restrict__ out, float* __restrict__ pred)
{
    __shared__ float sU[NC_ * HD_ + NC_];                 // U_W + U_b
    __shared__ __align__(16) float hbuf[4][2][32];        // per-warp h exchange (dbl buf)
    __shared__ __align__(16) float xbuf[4][2][32];        // per-warp x staging (dbl buf)

    for (int i = threadIdx.x; i < NC_ * HD_; i += blockDim.x) sU[i] = uW[i];
    for (int i = threadIdx.x; i < NC_;       i += blockDim.x) sU[NC_ * HD_ + i] = ubv[i];
    __syncthreads();

    const int lane = threadIdx.x & 31;
    const int w    = threadIdx.x >> 5;
    const int b    = blockIdx.x * 4 + w;

    // ---------- decoder weights -> registers (lane j owns unit j; clamp 28-31) ----------
    const int j = (lane < HD_) ? lane : (HD_ - 1);
    ull   dwhh[4][14];
    ull   dwih[4][2];
    float dbv[4];
#pragma unroll
    for (int g = 0; g < 4; ++g) {
        const float4* r4 = (const float4*)(dWhh + (size_t)(g * HD_ + j) * HD_);
#pragma unroll
        for (int q = 0; q < 7; ++q) {
            float4 v = __ldg(r4 + q);
            dwhh[g][2 * q]     = pack2(v.x, v.y);
            dwhh[g][2 * q + 1] = pack2(v.z, v.w);
        }
        float4 u = __ldg((const float4*)(dWih + (g * HD_ + j) * 4));
        dwih[g][0] = pack2(u.x, u.y);
        dwih[g][1] = pack2(u.z, u.w);
        dbv[g] = __ldg(db + g * HD_ + j);
    }

    // ---------- encoder weights -> registers (lane r = lane&15 owns gate-row r) ----------
    const int r = lane & 15;
    ull   ewih[14];
    ull   ewhh[2];
    float ebv;
    {
        const float4* r4 = (const float4*)(eWih + (size_t)r * IN_);
#pragma unroll
        for (int q = 0; q < 7; ++q) {
            float4 v = __ldg(r4 + q);
            ewih[2 * q]     = pack2(v.x, v.y);
            ewih[2 * q + 1] = pack2(v.z, v.w);
        }
        float4 u = __ldg((const float4*)(eWhh + r * 4));
        ewhh[0] = pack2(u.x, u.y);
        ewhh[1] = pack2(u.z, u.w);
        ebv = __ldg(eb + r);
    }

    // ---------- state ----------
    ull hd[14];
#pragma unroll
    for (int m = 0; m < 14; ++m) hd[m] = 0ull;
    ull   he01 = 0ull, he23 = 0ull;
    float cd = 0.f, ce = 0.f;

    const float* xrow = x + (size_t)b * T_ * IN_;
    float*       ob   = out + (size_t)b * T_ * HD_;

    // preload x[0]
    if (lane < IN_) xbuf[w][0][lane] = __ldg(xrow + lane);
    __syncwarp();

#pragma unroll 1
    for (int t = 0; t < T_; ++t) {
        // prefetch next x (LDG issued at top; consumed next iteration)
        float xn = 0.f;
        if (t + 1 < T_ && lane < IN_) xn = __ldg(xrow + (t + 1) * IN_ + lane);

        // ================= encoder (gate-parallel across lanes) =================
        const ulonglong2* xv = (const ulonglong2*)xbuf[w][t & 1];
        ull acc = pack2(ebv, 0.f);
#pragma unroll
        for (int q = 0; q < 7; ++q) {
            ulonglong2 xq = xv[q];
            fma2(acc, ewih[2 * q],     xq.x);
            fma2(acc, ewih[2 * q + 1], xq.y);
        }
        fma2(acc, ewhh[0], he01);
        fma2(acc, ewhh[1], he23);
        float gpre = hadd2(acc);
        // rows 0-7 (i,f) and 12-15 (o): sigmoid; rows 8-11 (g): tanh
        float gact = (r >= 8 && r < 12) ? tanh_f(gpre) : sigm(gpre);
        // gather activated gates of unit u = lane&3 (valid on every lane)
        float ai = __shfl_sync(0xffffffffu, gact, (lane & 3),      32);
        float af = __shfl_sync(0xffffffffu, gact, (lane & 3) + 4,  32);
        float ag = __shfl_sync(0xffffffffu, gact, (lane & 3) + 8,  32);
        float ao = __shfl_sync(0xffffffffu, gact, (lane & 3) + 12, 32);
        float cen = af * ce + ai * ag;      // every lane redundantly tracks unit lane&3
        ce = cen;
        float henew = ao * tanh_f(cen);
        he01 = pack2(__shfl_sync(0xffffffffu, henew, 0, 32),
                     __shfl_sync(0xffffffffu, henew, 1, 32));
        he23 = pack2(__shfl_sync(0xffffffffu, henew, 2, 32),
                     __shfl_sync(0xffffffffu, henew, 3, 32));

        // ================= decoder (lane j owns unit j) =================
        ull a0 = pack2(dbv[0], 0.f);
        ull a1 = pack2(dbv[1], 0.f);
        ull a2 = pack2(dbv[2], 0.f);
        ull a3 = pack2(dbv[3], 0.f);
        fma2(a0, dwih[0][0], he01); fma2(a0, dwih[0][1], he23);
        fma2(a1, dwih[1][0], he01); fma2(a1, dwih[1][1], he23);
        fma2(a2, dwih[2][0], he01); fma2(a2, dwih[2][1], he23);
        fma2(a3, dwih[3][0], he01); fma2(a3, dwih[3][1], he23);
#pragma unroll
        for (int m = 0; m < 14; ++m) {
            ull hm = hd[m];
            fma2(a0, dwhh[0][m], hm);
            fma2(a1, dwhh[1][m], hm);
            fma2(a2, dwhh[2][m], hm);
            fma2(a3, dwhh[3][m], hm);
        }
        float gi = hadd2(a0), gf = hadd2(a1), gg = hadd2(a2), go = hadd2(a3);
        float c  = sigm(gf) * cd + sigm(gi) * tanh_f(gg);
        cd = c;
        float h  = sigm(go) * tanh_f(c);

        if (lane < HD_) {
            ob[t * HD_ + lane]  = h;        // coalesced 112B per warp
            hbuf[w][t & 1][lane] = h;
            if (t + 1 < T_) xbuf[w][(t + 1) & 1][lane] = xn;
        }
        __syncwarp();

        // reload full packed h-state (uniform-address broadcast LDS.128)
        const ulonglong2* hv = (const ulonglong2*)hbuf[w][t & 1];
#pragma unroll
        for (int m = 0; m < 7; ++m) {
            ulonglong2 v = hv[m];
            hd[2 * m]     = v.x;
            hd[2 * m + 1] = v.y;
        }
    }

    // ================= classifier head + softmax (lanes 0-9) =================
    {
        const int k = (lane < NC_) ? lane : (NC_ - 1);
        const ull* uwk = (const ull*)(sU + k * HD_);    // 8B-aligned (112B rows)
        ull a = pack2(sU[NC_ * HD_ + k], 0.f);
#pragma unroll
        for (int m = 0; m < 14; ++m) fma2(a, uwk[m], hd[m]);
        float lg = hadd2(a);

        float lv = (lane < NC_) ? lg : -3.4e38f;
#pragma unroll
        for (int off = 8; off >= 1; off >>= 1)
            lv = fmaxf(lv, __shfl_xor_sync(0xffffffffu, lv, off, 16));
        float e = (lane < NC_) ? __expf(lg - lv) : 0.f;
        float s = e;
#pragma unroll
        for (int off = 8; off >= 1; off >>= 1)
            s += __shfl_xor_sync(0xffffffffu, s, off, 16);
        if (lane < NC_)
            pred[(size_t)b * NC_ + lane] = e * __fdividef(1.0f, s);
    }
}

extern "C" void kernel_launch(void* const* d_in, const int* in_sizes, int n_in,
                              void* d_out, int out_size)
{
    const float* x    = (const float*)d_in[0];
    const float* eWih = (const float*)d_in[1];
    const float* eWhh = (const float*)d_in[2];
    const float* eb   = (const float*)d_in[3];
    const float* dWih = (const float*)d_in[4];
    const float* dWhh = (const float*)d_in[5];
    const float* db   = (const float*)d_in[6];
    const float* uW   = (const float*)d_in[7];
    const float* ub   = (const float*)d_in[8];

    float* out  = (float*)d_out;                 // [B, T, 28]
    float* pred = out + (size_t)B_ * T_ * HD_;   // [1, B, 10]

    dim3 grid(B_ / 4), block(128);               // 1 warp per sample
    ae_lstm_kernel<<<grid, block>>>(x, eWih, eWhh, eb, dWih, dWhh, db, uW, ub,
                                    out, pred);
}

// round 4
// speedup vs baseline: 1.3929x; 1.0978x over previous
#include <cuda_runtime.h>

#define B_  65536
#define T_  28
#define IN_ 28
#define HD_ 28
#define NC_ 10

typedef unsigned long long ull;

__device__ __forceinline__ ull pack2(float lo, float hi) {
    ull r; asm("mov.b64 %0, {%1, %2};" : "=l"(r) : "f"(lo), "f"(hi)); return r;
}
__device__ __forceinline__ void fma2(ull& acc, ull a, ull b) {
    asm("fma.rn.f32x2 %0, %1, %2, %0;" : "+l"(acc) : "l"(a), "l"(b));
}
__device__ __forceinline__ float hadd2(ull v) {
    float lo, hi; asm("mov.b64 {%0, %1}, %2;" : "=f"(lo), "=f"(hi) : "l"(v));
    return lo + hi;
}
__device__ __forceinline__ float tanh_a(float v) {
    float r; asm("tanh.approx.f32 %0, %1;" : "=f"(r) : "f"(v)); return r;
}
__device__ __forceinline__ float sigm(float v) {
    return fmaf(0.5f, tanh_a(0.5f * v), 0.5f);
}

// decoder step for unit j (weights in regs), hd consumed straight from smem row
__device__ __forceinline__ float dec_step(const ull (&dwhh)[4][14], const ull (&dwih)[4][2],
                                          const float (&dbv)[4], ull hp0, ull hp1,
                                          const float* hrow, float& cd)
{
    const ulonglong2* hv = (const ulonglong2*)hrow;
    ull a0 = pack2(dbv[0], 0.f);
    ull a1 = pack2(dbv[1], 0.f);
    ull a2 = pack2(dbv[2], 0.f);
    ull a3 = pack2(dbv[3], 0.f);
    fma2(a0, dwih[0][0], hp0); fma2(a0, dwih[0][1], hp1);
    fma2(a1, dwih[1][0], hp0); fma2(a1, dwih[1][1], hp1);
    fma2(a2, dwih[2][0], hp0); fma2(a2, dwih[2][1], hp1);
    fma2(a3, dwih[3][0], hp0); fma2(a3, dwih[3][1], hp1);
#pragma unroll
    for (int m = 0; m < 7; ++m) {
        ulonglong2 v = hv[m];
        fma2(a0, dwhh[0][2*m], v.x); fma2(a0, dwhh[0][2*m+1], v.y);
        fma2(a1, dwhh[1][2*m], v.x); fma2(a1, dwhh[1][2*m+1], v.y);
        fma2(a2, dwhh[2][2*m], v.x); fma2(a2, dwhh[2][2*m+1], v.y);
        fma2(a3, dwhh[3][2*m], v.x); fma2(a3, dwhh[3][2*m+1], v.y);
    }
    float gi = hadd2(a0), gf = hadd2(a1), gg = hadd2(a2), go = hadd2(a3);
    float c  = sigm(gf) * cd + sigm(gi) * tanh_a(gg);
    cd = c;
    return sigm(go) * tanh_a(c);
}

// encoder step: half-warp-split dot product, gate-parallel, branchless activation
__device__ __forceinline__ void enc_step(const ull (&ew)[8], float ebv_eff, int xoff,
                                         float actA, float actB, float actC, int u,
                                         const float* xrow,
                                         ull& he01, ull& he23, float& ce)
{
    const ulonglong2* xp = (const ulonglong2*)xrow + xoff;
    ulonglong2 v0 = xp[0], v1 = xp[1], v2 = xp[2], v3 = xp[3];
    ull o6 = xoff ? he01 : v3.x;
    ull o7 = xoff ? he23 : v3.y;
    ull acc0 = pack2(ebv_eff, 0.f);
    ull acc1 = pack2(0.f, 0.f);
    fma2(acc0, ew[0], v0.x); fma2(acc1, ew[1], v0.y);
    fma2(acc0, ew[2], v1.x); fma2(acc1, ew[3], v1.y);
    fma2(acc0, ew[4], v2.x); fma2(acc1, ew[5], v2.y);
    fma2(acc0, ew[6], o6);   fma2(acc1, ew[7], o7);
    float s = hadd2(acc0) + hadd2(acc1);
    s += __shfl_xor_sync(0xffffffffu, s, 16, 32);
    float gact = fmaf(actA, tanh_a(actB * s), actC);   // sigm or tanh per lane
    float ai = __shfl_sync(0xffffffffu, gact, u,      32);
    float af = __shfl_sync(0xffffffffu, gact, u + 4,  32);
    float ag = __shfl_sync(0xffffffffu, gact, u + 8,  32);
    float ao = __shfl_sync(0xffffffffu, gact, u + 12, 32);
    float cen = af * ce + ai * ag;      // each lane tracks unit u = lane&3 (redundant)
    ce = cen;
    float hn = ao * tanh_a(cen);
    he01 = pack2(__shfl_sync(0xffffffffu, hn, 0, 32),
                 __shfl_sync(0xffffffffu, hn, 1, 32));
    he23 = pack2(__shfl_sync(0xffffffffu, hn, 2, 32),
                 __shfl_sync(0xffffffffu, hn, 3, 32));
}

__global__ void __launch_bounds__(128, 2)
ae_lstm_kernel(const float* __restrict__ x,
               const float* __restrict__ eWih, const float* __restrict__ eWhh,
               const float* __restrict__ eb,
               const float* __restrict__ dWih, const float* __restrict__ dWhh,
               const float* __restrict__ db,
               const float* __restrict__ uW,  const float* __restrict__ ubv,
               float* __restrict__ out, float* __restrict__ pred)
{
    __shared__ float sU[NC_ * HD_ + NC_];
    __shared__ __align__(16) float hbuf[4][2][32];
    __shared__ __align__(16) float xbuf[4][2][32];

    for (int i = threadIdx.x; i < NC_ * HD_; i += blockDim.x) sU[i] = uW[i];
    for (int i = threadIdx.x; i < NC_;       i += blockDim.x) sU[NC_ * HD_ + i] = ubv[i];
    __syncthreads();

    const int lane = threadIdx.x & 31;
    const int w    = threadIdx.x >> 5;
    const int b    = blockIdx.x * 4 + w;

    // ---------- decoder weights -> registers (lane j owns unit j; clamp 28-31) ----------
    const int j = (lane < HD_) ? lane : (HD_ - 1);
    ull   dwhh[4][14];
    ull   dwih[4][2];
    float dbv[4];
#pragma unroll
    for (int g = 0; g < 4; ++g) {
        const float4* r4 = (const float4*)(dWhh + (size_t)(g * HD_ + j) * HD_);
#pragma unroll
        for (int q = 0; q < 7; ++q) {
            float4 v = __ldg(r4 + q);
            dwhh[g][2 * q]     = pack2(v.x, v.y);
            dwhh[g][2 * q + 1] = pack2(v.z, v.w);
        }
        float4 u4 = __ldg((const float4*)(dWih + (g * HD_ + j) * 4));
        dwih[g][0] = pack2(u4.x, u4.y);
        dwih[g][1] = pack2(u4.z, u4.w);
        dbv[g] = __ldg(db + g * HD_ + j);
    }

    // ---------- encoder weights (half-warp split; lane r = lane&15 owns row r) ----------
    const int r = lane & 15;
    const int u = lane & 3;
    const int xoff = (lane < 16) ? 0 : 4;
    ull   ew[8];
    float ebv_eff;
    {
        const float2* p = (const float2*)(eWih + (size_t)r * IN_);
        if (lane < 16) {
#pragma unroll
            for (int m = 0; m < 8; ++m) { float2 v = __ldg(p + m); ew[m] = pack2(v.x, v.y); }
            ebv_eff = __ldg(eb + r);
        } else {
#pragma unroll
            for (int m = 0; m < 6; ++m) { float2 v = __ldg(p + 8 + m); ew[m] = pack2(v.x, v.y); }
            const float2* ph = (const float2*)(eWhh + r * 4);
            float2 h0 = __ldg(ph), h1 = __ldg(ph + 1);
            ew[6] = pack2(h0.x, h0.y);
            ew[7] = pack2(h1.x, h1.y);
            ebv_eff = 0.f;
        }
    }
    // branchless activation constants: rows 8-11 (g-gate) -> tanh, else sigmoid
    const bool  isg  = (r >= 8 && r < 12);
    const float actA = isg ? 1.0f : 0.5f;
    const float actB = isg ? 1.0f : 0.5f;
    const float actC = isg ? 0.0f : 0.5f;

    // ---------- state ----------
    ull   he01 = 0ull, he23 = 0ull;
    float cd = 0.f, ce = 0.f;

    const float* xrow = x + (size_t)b * T_ * IN_;
    float*       ob   = out + (size_t)b * T_ * HD_;

    // ---------- prologue: stage x0,x1; zero hd_{-1}; enc(0) ----------
    if (lane < IN_) {
        xbuf[w][0][lane] = __ldg(xrow + lane);
        xbuf[w][1][lane] = __ldg(xrow + IN_ + lane);
        hbuf[w][1][lane] = 0.f;
    }
    __syncwarp();
    enc_step(ew, ebv_eff, xoff, actA, actB, actC, u, xbuf[w][0], he01, he23, ce);

    // ---------- pipelined main loop: body(t) = dec(t-1) || enc(t) ----------
#pragma unroll 1
    for (int t = 1; t < T_; ++t) {
        ull hp0 = he01, hp1 = he23;                     // he_{t-1}
        float xn = 0.f;
        if (t + 1 < T_ && lane < IN_) xn = __ldg(xrow + (t + 1) * IN_ + lane);

        float h = dec_step(dwhh, dwih, dbv, hp0, hp1, hbuf[w][t & 1], cd);
        enc_step(ew, ebv_eff, xoff, actA, actB, actC, u, xbuf[w][t & 1], he01, he23, ce);

        if (lane < HD_) {
            ob[(t - 1) * HD_ + lane]     = h;
            hbuf[w][(t - 1) & 1][lane]   = h;
            if (t + 1 < T_) xbuf[w][(t + 1) & 1][lane] = xn;
        }
        __syncwarp();
    }

    // ---------- epilogue: dec(27) ----------
    {
        float h = dec_step(dwhh, dwih, dbv, he01, he23, hbuf[w][0], cd);
        if (lane < HD_) {
            ob[(T_ - 1) * HD_ + lane] = h;
            hbuf[w][1][lane] = h;
        }
        __syncwarp();
    }

    // ---------- classifier head + softmax ----------
    {
        ull hd[14];
        const ulonglong2* hv = (const ulonglong2*)hbuf[w][1];
#pragma unroll
        for (int m = 0; m < 7; ++m) { ulonglong2 v = hv[m]; hd[2*m] = v.x; hd[2*m+1] = v.y; }

        const int k = (lane < NC_) ? lane : (NC_ - 1);
        const ull* uwk = (const ull*)(sU + k * HD_);
        ull a = pack2(sU[NC_ * HD_ + k], 0.f);
#pragma unroll
        for (int m = 0; m < 14; ++m) fma2(a, uwk[m], hd[m]);
        float lg = hadd2(a);

        float lv = (lane < NC_) ? lg : -3.4e38f;
#pragma unroll
        for (int off = 8; off >= 1; off >>= 1)
            lv = fmaxf(lv, __shfl_xor_sync(0xffffffffu, lv, off, 16));
        float e = (lane < NC_) ? __expf(lg - lv) : 0.f;
        float s = e;
#pragma unroll
        for (int off = 8; off >= 1; off >>= 1)
            s += __shfl_xor_sync(0xffffffffu, s, off, 16);
        if (lane < NC_)
            pred[(size_t)b * NC_ + lane] = e * __fdividef(1.0f, s);
    }
}

extern "C" void kernel_launch(void* const* d_in, const int* in_sizes, int n_in,
                              void* d_out, int out_size)
{
    const float* x    = (const float*)d_in[0];
    const float* eWih = (const float*)d_in[1];
    const float* eWhh = (const float*)d_in[2];
    const float* eb   = (const float*)d_in[3];
    const float* dWih = (const float*)d_in[4];
    const float* dWhh = (const float*)d_in[5];
    const float* db   = (const float*)d_in[6];
    const float* uW   = (const float*)d_in[7];
    const float* ub   = (const float*)d_in[8];

    float* out  = (float*)d_out;                 // [B, T, 28]
    float* pred = out + (size_t)B_ * T_ * HD_;   // [1, B, 10]

    dim3 grid(B_ / 4), block(128);               // 1 warp per sample
    ae_lstm_kernel<<<grid, block>>>(x, eWih, eWhh, eb, dWih, dWhh, db, uW, ub,
                                    out, pred);
}